// round 16
// baseline (speedup 1.0000x reference)
#include <cuda_runtime.h>
#include <cuda_fp16.h>
#include <cstdint>

// ---------------- problem constants ----------------
#define Bb   256
#define Tt   512
#define Ii   64
#define Hh   512
#define NTHR 128     // 4 compute warps (2M x 2N, warp tile M16xN32); no DMA warp

// SMEM: W only
#define OFF_WH   0            // W_hh slice (fp16): [64 c][1024 B] = 64KB
#define OFF_WX   65536        // W_ih slice: [64 c][128 B] = 8KB
#define DSM_BYTES (73728 + 1024)

// ---------------- persistent device state ----------------
// h: [buf][group][32 rows][512 units] fp16 row-major (1KB/row); group = 32 batch rows
__device__ __align__(128) __half g_h[2][8][32 * 512];
// x: [t][group][32 rows][64 k] fp16 row-major (128B/row)
__device__ __align__(128) __half g_x[Tt][8][32 * 64];
__device__ float    g_hfinal[Bb][Hh];
__device__ unsigned g_cnt[8][4][16];   // [group][kchunk], padded to 64B

// ---------------- PTX helpers ----------------
__device__ __forceinline__ uint32_t smem_u32(const void* p) {
    uint32_t a;
    asm("{ .reg .u64 t; cvta.to.shared.u64 t, %1; cvt.u32.u64 %0, t; }" : "=r"(a) : "l"(p));
    return a;
}
__device__ __forceinline__ void ldsm4(uint32_t& a, uint32_t& b, uint32_t& c, uint32_t& d, uint32_t addr) {
    asm volatile("ldmatrix.sync.aligned.m8n8.x4.shared.b16 {%0,%1,%2,%3}, [%4];"
                 : "=r"(a), "=r"(b), "=r"(c), "=r"(d) : "r"(addr));
}
__device__ __forceinline__ uint32_t ldcg32(const void* p) {
    uint32_t v;
    asm volatile("ld.global.cg.b32 %0, [%1];" : "=r"(v) : "l"(p));
    return v;
}
// f32-accum fp16 MMA (x chunk)
__device__ __forceinline__ void mma16816(float* c, uint32_t a0, uint32_t a1, uint32_t a2, uint32_t a3,
                                         uint32_t b0, uint32_t b1) {
    asm volatile("mma.sync.aligned.m16n8k16.row.col.f32.f16.f16.f32 "
                 "{%0,%1,%2,%3}, {%4,%5,%6,%7}, {%8,%9}, {%0,%1,%2,%3};"
                 : "+f"(c[0]), "+f"(c[1]), "+f"(c[2]), "+f"(c[3])
                 : "r"(a0), "r"(a1), "r"(a2), "r"(a3), "r"(b0), "r"(b1));
}
// f16-accum fp16 MMA (h chunks)
__device__ __forceinline__ void mma16816h(uint32_t* c, uint32_t a0, uint32_t a1, uint32_t a2, uint32_t a3,
                                          uint32_t b0, uint32_t b1) {
    asm volatile("mma.sync.aligned.m16n8k16.row.col.f16.f16.f16.f16 "
                 "{%0,%1}, {%2,%3,%4,%5}, {%6,%7}, {%0,%1};"
                 : "+r"(c[0]), "+r"(c[1])
                 : "r"(a0), "r"(a1), "r"(a2), "r"(a3), "r"(b0), "r"(b1));
}
__device__ __forceinline__ void poll_cnt(const unsigned* cnt, unsigned target) {
    unsigned v;
    do {
        asm volatile("ld.acquire.gpu.global.u32 %0, [%1];" : "=r"(v) : "l"(cnt) : "memory");
    } while (v < target);
}

// ---------------- activations ----------------
__device__ __forceinline__ float sigm(float x) { return __fdividef(1.f, 1.f + __expf(-x)); }
__device__ __forceinline__ float tanh_(float x) {
    x = fminf(fmaxf(x, -15.f), 15.f);
    float e = __expf(2.f * x);
    return __fdividef(e - 1.f, e + 1.f);
}

// ---------------- h-chunk GEMM: A frags via ld.global.cg, W via ldsm; fp16 accum ----------------
// hA: group h base (row-major [32][512]); chunk kc covers k in [kc*128, kc*128+128).
__device__ __forceinline__ void chunk_h_g(const __half* hA, uint32_t Whi, int kc,
                                          uint32_t (&acc16)[4][2], int lane, int m0) {
    const int r0 = m0 + (lane >> 2);
    const int kc0 = (lane & 3) * 2;
    const int cB = (lane & 7) + ((lane & 16) >> 1);
    const int kB = (lane >> 3) & 1;
    const int xr = lane & 7;
#pragma unroll
    for (int s = 0; s < 8; s++) {
        const int kg = kc * 128 + s * 16 + kc0;
        const __half* pr = hA + r0 * 512 + kg;
        uint32_t a0 = ldcg32(pr);
        uint32_t a1 = ldcg32(pr + 8 * 512);
        uint32_t a2 = ldcg32(pr + 8);
        uint32_t a3 = ldcg32(pr + 8 * 512 + 8);
        const int kcW = kc * 16 + s * 2;
        uint32_t b01 = Whi + cB * 1024 + (((kcW + kB) ^ xr) << 4);
        uint32_t bh[8];
        ldsm4(bh[0], bh[1], bh[2], bh[3], b01);
        ldsm4(bh[4], bh[5], bh[6], bh[7], b01 + 16 * 1024);
#pragma unroll
        for (int ti = 0; ti < 4; ti++)
            mma16816h(acc16[ti], a0, a1, a2, a3, bh[2 * ti], bh[2 * ti + 1]);
    }
}

// ---------------- x GEMM: A frags via __ldg (immutable), f32 accum ----------------
__device__ __forceinline__ void chunk_x_g(const __half* xA, uint32_t Whi,
                                          float (&acc)[4][4], int lane, int m0) {
    const int r0 = m0 + (lane >> 2);
    const int kc0 = (lane & 3) * 2;
    const int cB = (lane & 7) + ((lane & 16) >> 1);
    const int kB = (lane >> 3) & 1;
    const int xr = lane & 7;
#pragma unroll
    for (int s = 0; s < 4; s++) {
        const int kg = s * 16 + kc0;
        const __half* pr = xA + r0 * 64 + kg;
        uint32_t a0 = __ldg(reinterpret_cast<const unsigned*>(pr));
        uint32_t a1 = __ldg(reinterpret_cast<const unsigned*>(pr + 8 * 64));
        uint32_t a2 = __ldg(reinterpret_cast<const unsigned*>(pr + 8));
        uint32_t a3 = __ldg(reinterpret_cast<const unsigned*>(pr + 8 * 64 + 8));
        uint32_t b01 = Whi + cB * 128 + (((s * 2 + kB) ^ xr) << 4);
        uint32_t bh[8];
        ldsm4(bh[0], bh[1], bh[2], bh[3], b01);
        ldsm4(bh[4], bh[5], bh[6], bh[7], b01 + 16 * 128);
#pragma unroll
        for (int ti = 0; ti < 4; ti++)
            mma16816(acc[ti], a0, a1, a2, a3, bh[2 * ti], bh[2 * ti + 1]);
    }
}

// ---------------- init: zero h buf0, reset counters, x -> fp16 layout ----------------
__global__ void init_kernel(const float* __restrict__ x) {
    int idx = blockIdx.x * blockDim.x + threadIdx.x;
    int stride = gridDim.x * blockDim.x;
    uint32_t* hz = reinterpret_cast<uint32_t*>(&g_h[0][0][0]);
    for (int i = idx; i < 8 * 32 * 512 / 2; i += stride) hz[i] = 0u;
    for (int i = idx; i < Bb * Tt * Ii; i += stride) {
        int k = i & 63;
        int t = (i >> 6) & 511;
        int b = i >> 15;
        g_x[t][b >> 5][(b & 31) * 64 + k] = __float2half(x[i]);
    }
    if (idx < 32) g_cnt[idx >> 2][idx & 3][0] = 0u;
}

// ---------------- persistent LSTM: direct-L2 fragment loads, no TMA ----------------
__global__ void __launch_bounds__(NTHR, 2) lstm_kernel(
    const float* __restrict__ W_ih,   // [2048, 64]
    const float* __restrict__ W_hh,   // [2048, 512]
    const float* __restrict__ b_ih,
    const float* __restrict__ b_hh)
{
    extern __shared__ char dsm[];
    __shared__ float s_bias[64];

    const int tid  = threadIdx.x;
    const int lane = tid & 31;
    const int wid  = tid >> 5;
    const int grp  = blockIdx.x >> 5;       // 8 groups x 32 batch rows
    const int nc   = blockIdx.x & 31;       // gate cols [nc*64, nc*64+64) -> 16 units

    uint32_t raw = smem_u32(dsm);
    uint32_t base = (raw + 1023u) & ~1023u;
    char* bptr = dsm + (base - raw);

    // ---- stage W slices (once), fp16, swizzled for ldsm ----
    for (int idx = tid; idx < 64 * Hh; idx += NTHR) {
        int c = idx >> 9, k = idx & 511;
        int row = (c & 3) * Hh + nc * 16 + (c >> 2);
        float w = W_hh[(size_t)row * Hh + k];
        unsigned off = (unsigned)c * 1024u + ((((unsigned)k >> 3) ^ (c & 7)) << 4) + (k & 7) * 2u;
        *reinterpret_cast<__half*>(bptr + OFF_WH + off) = __float2half(w);
    }
    for (int idx = tid; idx < 64 * Ii; idx += NTHR) {
        int c = idx >> 6, k = idx & 63;
        int row = (c & 3) * Hh + nc * 16 + (c >> 2);
        float w = W_ih[(size_t)row * Ii + k];
        unsigned off = (unsigned)c * 128u + ((((unsigned)k >> 3) ^ (c & 7)) << 4) + (k & 7) * 2u;
        *reinterpret_cast<__half*>(bptr + OFF_WX + off) = __float2half(w);
    }
    if (tid < 64) {
        int row = (tid & 3) * Hh + nc * 16 + (tid >> 2);
        s_bias[tid] = b_ih[row] + b_hh[row];
    }
    __syncthreads();

    // warp mapping: 2(M) x 2(N), warp tile M16xN32
    const int m0 = (wid >> 1) * 16;
    const int nh = wid & 1;
    const uint32_t WhW = base + OFF_WH + nh * 32 * 1024;
    const uint32_t WxW = base + OFF_WX + nh * 32 * 128;

    // shuffle-epilogue mapping: thread -> 1 row x 4 unit-quads
    const int cgrp = lane & 3;
    const int odd  = cgrp & 1;
    const int erow = m0 + (lane >> 2) + (odd ? 8 : 0);   // local batch row 0..31
    int uloc[4];
    float bia[4][4];
#pragma unroll
    for (int ti = 0; ti < 4; ti++) {
        uloc[ti] = nh * 8 + ti * 2 + (cgrp >> 1);        // local unit 0..15
#pragma unroll
        for (int g = 0; g < 4; g++) bia[ti][g] = s_bias[uloc[ti] * 4 + g];
    }
    unsigned* mycnt = &g_cnt[grp][nc >> 3][0];
    const unsigned* ccnt[4] = { &g_cnt[grp][0][0], &g_cnt[grp][1][0],
                                &g_cnt[grp][2][0], &g_cnt[grp][3][0] };

    float cs[4] = {0.f, 0.f, 0.f, 0.f};

#pragma unroll 1
    for (int t = 0; t < Tt; t++) {
        const int rb = t & 1, wb = rb ^ 1;
        const __half* hA = &g_h[rb][grp][0];
        const __half* xA = &g_x[t][grp][0];

        float acc[4][4];
#pragma unroll
        for (int a = 0; a < 4; a++)
#pragma unroll
            for (int b = 0; b < 4; b++) acc[a][b] = 0.f;

        // x contribution (f32 accum) — no dependency, runs while producers' reds land
        chunk_x_g(xA, WxW, acc, lane, m0);

        // h chunks: poll producer counter, then direct-L2 fragment loads, fp16 accum
        const unsigned target = (unsigned)t * 8u;
#pragma unroll
        for (int kc = 0; kc < 4; kc++) {
            if (t > 0) poll_cnt(ccnt[kc], target);
            uint32_t a16[4][2];
#pragma unroll
            for (int a = 0; a < 4; a++) { a16[a][0] = 0u; a16[a][1] = 0u; }
            chunk_h_g(hA, WhW, kc, a16, lane, m0);
#pragma unroll
            for (int a = 0; a < 4; a++) {
                float2 lo = __half22float2(*reinterpret_cast<__half2*>(&a16[a][0]));
                float2 hi = __half22float2(*reinterpret_cast<__half2*>(&a16[a][1]));
                acc[a][0] += lo.x; acc[a][1] += lo.y;
                acc[a][2] += hi.x; acc[a][3] += hi.y;
            }
        }

        // ---- shuffle epilogue: one (row, unit-quad) per thread per ti ----
        __half* const hdst = &g_h[wb][grp][0];
#pragma unroll
        for (int ti = 0; ti < 4; ti++) {
            float e0 = __shfl_xor_sync(0xffffffffu, acc[ti][0], 1);
            float e1 = __shfl_xor_sync(0xffffffffu, acc[ti][1], 1);
            float e2 = __shfl_xor_sync(0xffffffffu, acc[ti][2], 1);
            float e3 = __shfl_xor_sync(0xffffffffu, acc[ti][3], 1);
            float gi, gf, gg, go;
            if (odd) { gi = e2;         gf = e3;         gg = acc[ti][2]; go = acc[ti][3]; }
            else     { gi = acc[ti][0]; gf = acc[ti][1]; gg = e0;         go = e1;         }
            float iv = sigm(gi + bia[ti][0]);
            float fv = sigm(gf + bia[ti][1]);
            float gv = tanh_(gg + bia[ti][2]);
            float ov = sigm(go + bia[ti][3]);
            cs[ti] = fv * cs[ti] + iv * gv;
            float hv = ov * tanh_(cs[ti]);
            hdst[erow * 512 + nc * 16 + uloc[ti]] = __float2half(hv);
            if (t == Tt - 1) g_hfinal[grp * 32 + erow][nc * 16 + uloc[ti]] = hv;
        }

        __syncthreads();   // all warps' h STGs issued before the release-add
        if (tid == 0 && t < Tt - 1)
            asm volatile("red.release.gpu.global.add.u32 [%0], %1;" :: "l"(mycnt), "r"(1u) : "memory");
    }
}

// ---------------- final FC ----------------
__global__ void fc_kernel(const float* __restrict__ W_fc,
                          const float* __restrict__ b_fc,
                          float* __restrict__ out) {
    int b = threadIdx.x;
    float s = 0.f;
#pragma unroll 8
    for (int k = 0; k < Hh; k++) s += g_hfinal[b][k] * W_fc[k];
    out[b] = s + b_fc[0];
}

extern "C" void kernel_launch(void* const* d_in, const int* in_sizes, int n_in,
                              void* d_out, int out_size) {
    const float* x    = (const float*)d_in[0];
    const float* W_ih = (const float*)d_in[1];
    const float* W_hh = (const float*)d_in[2];
    const float* b_ih = (const float*)d_in[3];
    const float* b_hh = (const float*)d_in[4];
    const float* W_fc = (const float*)d_in[5];
    const float* b_fc = (const float*)d_in[6];
    float* out = (float*)d_out;

    cudaFuncSetAttribute(lstm_kernel, cudaFuncAttributeMaxDynamicSharedMemorySize, DSM_BYTES);

    init_kernel<<<1024, 256>>>(x);
    lstm_kernel<<<256, NTHR, DSM_BYTES>>>(W_ih, W_hh, b_ih, b_hh);
    fc_kernel<<<1, Bb>>>(W_fc, b_fc, out);
}

// round 17
// speedup vs baseline: 1.5146x; 1.5146x over previous
#include <cuda_runtime.h>
#include <cuda_fp16.h>
#include <cstdint>

// ---------------- problem constants ----------------
#define Bb   256
#define Tt   512
#define Ii   64
#define Hh   512
#define NTHR 160     // 4 compute warps (2M x 2N, warp tile M16xN32) + 1 DMA warp

// SMEM layout offsets (from 1024-aligned base)
#define OFF_WH   0            // W_hh slice (fp16): [64 c][1024 B] = 64KB
#define OFF_WX   65536        // W_ih slice: [64 c][128 B] = 8KB
#define OFF_A    73728        // 4 h chunk bufs, 8KB each (fp16, 32 rows x 256B)
#define OFF_XB   106496       // x buf: 4KB (32 rows x 128B)
#define DSM_BYTES (110592 + 1024)

// ---------------- persistent device state ----------------
// h tile layout: [buf][group][kchunk][8KB]; group = 32 batch rows (8 groups)
// chunk = 32 rows x 128 units fp16 (256B/row), 16B-chunk swizzle
__device__ __align__(1024) unsigned char g_hblk[2][8][4][8192];
// x tile layout: [t][group][4KB] = 32 rows x 64 fp16 (128B/row), swizzled
__device__ __align__(1024) unsigned char g_xblk[Tt][8][4096];
__device__ float    g_hfinal[Bb][Hh];
__device__ unsigned g_cnt[8][4][16];   // [group][kchunk], padded to 64B

// ---------------- PTX helpers ----------------
__device__ __forceinline__ uint32_t smem_u32(const void* p) {
    uint32_t a;
    asm("{ .reg .u64 t; cvta.to.shared.u64 t, %1; cvt.u32.u64 %0, t; }" : "=r"(a) : "l"(p));
    return a;
}
#define MBARRIER_INIT(sa, cnt) \
    asm volatile("mbarrier.init.shared.b64 [%0], %1;" :: "r"((uint32_t)(sa)), "r"((uint32_t)(cnt)) : "memory")
#define MBARRIER_ARRIVE(sa) \
    asm volatile("mbarrier.arrive.shared.b64 _, [%0];" :: "r"((uint32_t)(sa)) : "memory")
#define MBAR_WAIT(sa, ph) do { \
    asm volatile("{\n\t.reg .pred P1;\n\tWL%=:\n\t" \
        "mbarrier.try_wait.parity.acquire.cta.shared::cta.b64 P1, [%0], %1, 0x989680;\n\t" \
        "@P1 bra.uni WD%=;\n\tbra.uni WL%=;\n\tWD%=:\n\t}" \
        :: "r"((uint32_t)(sa)), "r"((uint32_t)(ph)) : "memory"); \
} while (0)
#define FENCE_PROXY_ASYNC() asm volatile("fence.proxy.async;" ::: "memory")

__device__ __forceinline__ void tma_issue(uint32_t dst, const void* src, uint32_t bytes, uint32_t mbar) {
    asm volatile("mbarrier.arrive.expect_tx.shared.b64 _, [%0], %1;"
                 :: "r"(mbar), "r"(bytes) : "memory");
    asm volatile("cp.async.bulk.shared::cta.global.mbarrier::complete_tx::bytes [%0], [%1], %2, [%3];"
                 :: "r"(dst), "l"(src), "r"(bytes), "r"(mbar) : "memory");
}
__device__ __forceinline__ void ldsm4(uint32_t& a, uint32_t& b, uint32_t& c, uint32_t& d, uint32_t addr) {
    asm volatile("ldmatrix.sync.aligned.m8n8.x4.shared.b16 {%0,%1,%2,%3}, [%4];"
                 : "=r"(a), "=r"(b), "=r"(c), "=r"(d) : "r"(addr));
}
// f32-accum fp16 MMA (x chunk)
__device__ __forceinline__ void mma16816(float* c, uint32_t a0, uint32_t a1, uint32_t a2, uint32_t a3,
                                         uint32_t b0, uint32_t b1) {
    asm volatile("mma.sync.aligned.m16n8k16.row.col.f32.f16.f16.f32 "
                 "{%0,%1,%2,%3}, {%4,%5,%6,%7}, {%8,%9}, {%0,%1,%2,%3};"
                 : "+f"(c[0]), "+f"(c[1]), "+f"(c[2]), "+f"(c[3])
                 : "r"(a0), "r"(a1), "r"(a2), "r"(a3), "r"(b0), "r"(b1));
}
// f16-accum fp16 MMA (h chunks)
__device__ __forceinline__ void mma16816h(uint32_t* c, uint32_t a0, uint32_t a1, uint32_t a2, uint32_t a3,
                                          uint32_t b0, uint32_t b1) {
    asm volatile("mma.sync.aligned.m16n8k16.row.col.f16.f16.f16.f16 "
                 "{%0,%1}, {%2,%3,%4,%5}, {%6,%7}, {%0,%1};"
                 : "+r"(c[0]), "+r"(c[1])
                 : "r"(a0), "r"(a1), "r"(a2), "r"(a3), "r"(b0), "r"(b1));
}
#define BAR_COMPUTE() asm volatile("bar.sync 1, 128;" ::: "memory")

// ---------------- activations ----------------
__device__ __forceinline__ float sigm(float x) { return __fdividef(1.f, 1.f + __expf(-x)); }
__device__ __forceinline__ float tanh_(float x) {
    x = fminf(fmaxf(x, -15.f), 15.f);
    float e = __expf(2.f * x);
    return __fdividef(e - 1.f, e + 1.f);
}

// ---------------- h-chunk GEMM: fp16 accum, warp tile M16xN32 ----------------
__device__ __forceinline__ void compute_chunk_h16(uint32_t Abase, uint32_t Whi,
                                                  int kw0, uint32_t (&acc16)[4][2],
                                                  int lane, int m0) {
    const int rA = m0 + (lane & 15);
    const int kA = lane >> 4;
    const int xr = lane & 7;
    const int cB = (lane & 7) + ((lane & 16) >> 1);
    const int kB = (lane >> 3) & 1;
#pragma unroll
    for (int s = 0; s < 8; s++) {
        const int kcA = s * 2;
        uint32_t aaddr = Abase + rA * 256 + (((kcA + kA) ^ xr) << 4);
        uint32_t a[4];
        ldsm4(a[0], a[1], a[2], a[3], aaddr);
        const int kcW = kw0 + s * 2;
        uint32_t b01 = Whi + cB * 1024 + (((kcW + kB) ^ xr) << 4);
        uint32_t bh[8];
        ldsm4(bh[0], bh[1], bh[2], bh[3], b01);
        ldsm4(bh[4], bh[5], bh[6], bh[7], b01 + 16 * 1024);
#pragma unroll
        for (int ti = 0; ti < 4; ti++)
            mma16816h(acc16[ti], a[0], a[1], a[2], a[3], bh[2 * ti], bh[2 * ti + 1]);
    }
}

// ---------------- x-chunk GEMM: f32 accum ----------------
__device__ __forceinline__ void compute_x(uint32_t Abase, uint32_t Whi,
                                          float (&acc)[4][4], int lane, int m0) {
    const int rA = m0 + (lane & 15);
    const int kA = lane >> 4;
    const int xr = lane & 7;
    const int cB = (lane & 7) + ((lane & 16) >> 1);
    const int kB = (lane >> 3) & 1;
#pragma unroll
    for (int s = 0; s < 4; s++) {
        uint32_t aaddr = Abase + rA * 128 + (((s * 2 + kA) ^ xr) << 4);
        uint32_t a[4];
        ldsm4(a[0], a[1], a[2], a[3], aaddr);
        uint32_t b01 = Whi + cB * 128 + (((s * 2 + kB) ^ xr) << 4);
        uint32_t bh[8];
        ldsm4(bh[0], bh[1], bh[2], bh[3], b01);
        ldsm4(bh[4], bh[5], bh[6], bh[7], b01 + 16 * 128);
#pragma unroll
        for (int ti = 0; ti < 4; ti++)
            mma16816(acc[ti], a[0], a[1], a[2], a[3], bh[2 * ti], bh[2 * ti + 1]);
    }
}

// ---------------- init: zero h buf0, reset counters, x -> fp16 tile layout ----------------
__global__ void init_kernel(const float* __restrict__ x) {
    int idx = blockIdx.x * blockDim.x + threadIdx.x;
    int stride = gridDim.x * blockDim.x;
    uint32_t* hz = reinterpret_cast<uint32_t*>(&g_hblk[0][0][0][0]);
    for (int i = idx; i < 8 * 4 * 8192 / 4; i += stride) hz[i] = 0u;
    for (int i = idx; i < Bb * Tt * Ii; i += stride) {
        int ii = i & 63;
        int t  = (i >> 6) & 511;
        int b  = i >> 15;
        int grp = b >> 5, m = b & 31;
        unsigned off = (unsigned)m * 128u + ((((unsigned)ii >> 3) ^ (m & 7)) << 4) + (ii & 7) * 2u;
        *reinterpret_cast<__half*>(&g_xblk[t][grp][off]) = __float2half(x[i]);
    }
    if (idx < 32) g_cnt[idx >> 2][idx & 3][0] = 0u;
}

// ---------------- persistent LSTM: occupancy-2 + anti-phase stagger ----------------
__global__ void __launch_bounds__(NTHR, 2) lstm_kernel(
    const float* __restrict__ W_ih,   // [2048, 64]
    const float* __restrict__ W_hh,   // [2048, 512]
    const float* __restrict__ b_ih,
    const float* __restrict__ b_hh)
{
    extern __shared__ char dsm[];
    // mbars: 0..3 full A[kc], 4 full X, 5..8 empty A[kc], 9 empty X
    __shared__ __align__(8) unsigned long long s_mb[10];
    __shared__ float s_bias[64];

    const int tid  = threadIdx.x;
    const int lane = tid & 31;
    const int wid  = tid >> 5;
    const int grp  = blockIdx.x >> 5;       // 8 groups x 32 batch rows
    const int nc   = blockIdx.x & 31;       // gate cols [nc*64, nc*64+64) -> 16 units

    uint32_t raw = smem_u32(dsm);
    uint32_t base = (raw + 1023u) & ~1023u;
    char* bptr = dsm + (base - raw);

    // ---- stage W slices (once), fp16, swizzled ----
    for (int idx = tid; idx < 64 * Hh; idx += NTHR) {
        int c = idx >> 9, k = idx & 511;
        int row = (c & 3) * Hh + nc * 16 + (c >> 2);
        float w = W_hh[(size_t)row * Hh + k];
        unsigned off = (unsigned)c * 1024u + ((((unsigned)k >> 3) ^ (c & 7)) << 4) + (k & 7) * 2u;
        *reinterpret_cast<__half*>(bptr + OFF_WH + off) = __float2half(w);
    }
    for (int idx = tid; idx < 64 * Ii; idx += NTHR) {
        int c = idx >> 6, k = idx & 63;
        int row = (c & 3) * Hh + nc * 16 + (c >> 2);
        float w = W_ih[(size_t)row * Ii + k];
        unsigned off = (unsigned)c * 128u + ((((unsigned)k >> 3) ^ (c & 7)) << 4) + (k & 7) * 2u;
        *reinterpret_cast<__half*>(bptr + OFF_WX + off) = __float2half(w);
    }
    if (tid < 64) {
        int row = (tid & 3) * Hh + nc * 16 + (tid >> 2);
        s_bias[tid] = b_ih[row] + b_hh[row];
    }
    if (tid == 0) {
#pragma unroll
        for (int i = 0; i < 5; i++)  MBARRIER_INIT(smem_u32(&s_mb[i]), 1);   // full (expect_tx)
#pragma unroll
        for (int i = 5; i < 10; i++) MBARRIER_INIT(smem_u32(&s_mb[i]), 4);   // empty (4 compute warps)
    }
    __syncthreads();

    // ---- anti-phase stagger: skew groups so co-resident CTAs (group offset 4-5)
    // land ~half a step apart; offsets are self-sustaining in the dataflow ----
    {
        long long tgt = clock64() + (long long)grp * 800;
        while (clock64() < tgt) { }
    }

    uint32_t fA[4], eA[4];
#pragma unroll
    for (int i = 0; i < 4; i++) { fA[i] = smem_u32(&s_mb[i]); eA[i] = smem_u32(&s_mb[5 + i]); }
    const uint32_t fx = smem_u32(&s_mb[4]), ex = smem_u32(&s_mb[9]);
    uint32_t Abuf[4];
#pragma unroll
    for (int i = 0; i < 4; i++) Abuf[i] = base + OFF_A + i * 8192;
    const uint32_t XB = base + OFF_XB;

    // =========================== DMA warp: lanes 0-3 own h chunks, lane 4 owns x ===========================
    if (wid == 4) {
        if (lane < 4) {
            volatile unsigned* cnt = &g_cnt[grp][lane][0];
            int pe = 1;
#pragma unroll 1
            for (int t = 0; t < Tt; t++) {
                const unsigned char* hsrc = &g_hblk[t & 1][grp][lane][0];
                const unsigned target = (unsigned)t * 8u;
                MBAR_WAIT(eA[lane], pe); pe ^= 1;
                unsigned v;
                do {
                    asm volatile("ld.acquire.gpu.global.u32 %0, [%1];" : "=r"(v) : "l"(cnt));
                } while (v < target);
                FENCE_PROXY_ASYNC();
                tma_issue(Abuf[lane], hsrc, 8192, fA[lane]);
            }
        } else if (lane == 4) {
            int pe = 1;
#pragma unroll 1
            for (int t = 0; t < Tt; t++) {
                MBAR_WAIT(ex, pe); pe ^= 1;
                FENCE_PROXY_ASYNC();
                tma_issue(XB, &g_xblk[t][grp][0], 4096, fx);
            }
        }
        return;
    }

    // =========================== compute warps: 2(M) x 2(N), warp tile M16xN32 ===========================
    const int m0 = (wid >> 1) * 16;
    const int nh = wid & 1;
    const uint32_t WhW = base + OFF_WH + nh * 32 * 1024;
    const uint32_t WxW = base + OFF_WX + nh * 32 * 128;

    // shuffle-epilogue mapping: thread -> 1 row x 4 unit-quads
    const int cgrp = lane & 3;
    const int odd  = cgrp & 1;
    const int erow = m0 + (lane >> 2) + (odd ? 8 : 0);   // local batch row 0..31
    int uloc[4];
    float bia[4][4];
#pragma unroll
    for (int ti = 0; ti < 4; ti++) {
        uloc[ti] = nh * 8 + ti * 2 + (cgrp >> 1);        // local unit 0..15
#pragma unroll
        for (int g = 0; g < 4; g++) bia[ti][g] = s_bias[uloc[ti] * 4 + g];
    }
    // h store addresses (chunk kcb = nc>>3 fixed per CTA)
    const int kcb = nc >> 3;
    unsigned hoff[4];
#pragma unroll
    for (int ti = 0; ti < 4; ti++) {
        unsigned ucol = (unsigned)((nc & 7) * 16 + uloc[ti]);
        hoff[ti] = (unsigned)erow * 256u + (((ucol >> 3) ^ (erow & 7)) << 4) + (ucol & 7) * 2u;
    }
    unsigned* mycnt = &g_cnt[grp][kcb][0];

    float cs[4] = {0.f, 0.f, 0.f, 0.f};
    int pfA[4] = {0, 0, 0, 0}, pfx = 0;

#pragma unroll 1
    for (int t = 0; t < Tt; t++) {
        const int wb = (t & 1) ^ 1;

        float acc[4][4];
#pragma unroll
        for (int a = 0; a < 4; a++)
#pragma unroll
            for (int b = 0; b < 4; b++) acc[a][b] = 0.f;

        // x chunk first (f32 accum)
        MBAR_WAIT(fx, pfx); pfx ^= 1;
        compute_x(XB, WxW, acc, lane, m0);
        if (lane == 0) MBARRIER_ARRIVE(ex);

        // h chunks: fp16 accum per chunk, promote to f32
#pragma unroll
        for (int kc = 0; kc < 4; kc++) {
            MBAR_WAIT(fA[kc], pfA[kc]); pfA[kc] ^= 1;
            uint32_t a16[4][2];
#pragma unroll
            for (int a = 0; a < 4; a++) { a16[a][0] = 0u; a16[a][1] = 0u; }
            compute_chunk_h16(Abuf[kc], WhW, kc * 16, a16, lane, m0);
            if (lane == 0) MBARRIER_ARRIVE(eA[kc]);
#pragma unroll
            for (int a = 0; a < 4; a++) {
                float2 lo = __half22float2(*reinterpret_cast<__half2*>(&a16[a][0]));
                float2 hi = __half22float2(*reinterpret_cast<__half2*>(&a16[a][1]));
                acc[a][0] += lo.x; acc[a][1] += lo.y;
                acc[a][2] += hi.x; acc[a][3] += hi.y;
            }
        }

        // ---- shuffle epilogue: one (row, unit-quad) per thread per ti ----
        unsigned char* const hdst = &g_hblk[wb][grp][kcb][0];
#pragma unroll
        for (int ti = 0; ti < 4; ti++) {
            float e0 = __shfl_xor_sync(0xffffffffu, acc[ti][0], 1);
            float e1 = __shfl_xor_sync(0xffffffffu, acc[ti][1], 1);
            float e2 = __shfl_xor_sync(0xffffffffu, acc[ti][2], 1);
            float e3 = __shfl_xor_sync(0xffffffffu, acc[ti][3], 1);
            float gi, gf, gg, go;
            if (odd) { gi = e2;         gf = e3;         gg = acc[ti][2]; go = acc[ti][3]; }
            else     { gi = acc[ti][0]; gf = acc[ti][1]; gg = e0;         go = e1;         }
            float iv = sigm(gi + bia[ti][0]);
            float fv = sigm(gf + bia[ti][1]);
            float gv = tanh_(gg + bia[ti][2]);
            float ov = sigm(go + bia[ti][3]);
            cs[ti] = fv * cs[ti] + iv * gv;
            float hv = ov * tanh_(cs[ti]);
            *reinterpret_cast<unsigned short*>(hdst + hoff[ti]) = __half_as_ushort(__float2half(hv));
            if (t == Tt - 1) g_hfinal[grp * 32 + erow][nc * 16 + uloc[ti]] = hv;
        }

        BAR_COMPUTE();     // all compute warps' h STGs done
        if (tid == 0 && t < Tt - 1)
            asm volatile("red.release.gpu.global.add.u32 [%0], %1;" :: "l"(mycnt), "r"(1u) : "memory");
    }
}

// ---------------- final FC ----------------
__global__ void fc_kernel(const float* __restrict__ W_fc,
                          const float* __restrict__ b_fc,
                          float* __restrict__ out) {
    int b = threadIdx.x;
    float s = 0.f;
#pragma unroll 8
    for (int k = 0; k < Hh; k++) s += g_hfinal[b][k] * W_fc[k];
    out[b] = s + b_fc[0];
}

extern "C" void kernel_launch(void* const* d_in, const int* in_sizes, int n_in,
                              void* d_out, int out_size) {
    const float* x    = (const float*)d_in[0];
    const float* W_ih = (const float*)d_in[1];
    const float* W_hh = (const float*)d_in[2];
    const float* b_ih = (const float*)d_in[3];
    const float* b_hh = (const float*)d_in[4];
    const float* W_fc = (const float*)d_in[5];
    const float* b_fc = (const float*)d_in[6];
    float* out = (float*)d_out;

    cudaFuncSetAttribute(lstm_kernel, cudaFuncAttributeMaxDynamicSharedMemorySize, DSM_BYTES);

    init_kernel<<<1024, 256>>>(x);
    lstm_kernel<<<256, NTHR, DSM_BYTES>>>(W_ih, W_hh, b_ih, b_hh);
    fc_kernel<<<1, Bb>>>(W_fc, b_fc, out);
}